// round 16
// baseline (speedup 1.0000x reference)
#include <cuda_runtime.h>
#include <cstdint>

// HeteroEmbedding: out[n] = tables[types[n], x[n]]  (row 0 zeroed -> mask implicit).
//
// Inputs: d_in[0] x int32[N], d_in[1] types int32[N], d_in[2] tables f32[8,50000,128]
// Output: f32[N,128]
//
// R13/R14 showed: direct gather is pinned at ~1.79GB DRAM traffic / ~85% util.
// Compulsory table reads are only ~203MB of the ~750MB we pay -> manufacture
// locality via counting sort by table-row bucket, then gather in bucket order
// so every ~5x row reuse hits L2. Scratch in __device__ globals (no allocs).

#define VOCAB 50000
#define EMBED 128
#define F4_PER_ROW (EMBED / 4)
#define NB 1024
#define SHIFT 9                 // bucket = table_row >> 9 ; 400000>>9 = 782 live buckets
#define MAXN 2000000

__device__ unsigned g_hist[NB];
__device__ unsigned g_cursors[NB];
__device__ uint2    g_records[MAXN];   // {table_row, n}

// ---------------- pass 0: zero (graph replays need fresh counters) ----------
__global__ void init_kernel()
{
    int t = blockIdx.x * blockDim.x + threadIdx.x;
    if (t < NB) { g_hist[t] = 0; g_cursors[t] = 0; }
}

// ---------------- pass 1: histogram (smem-privatized) -----------------------
__global__ void __launch_bounds__(256)
hist_kernel(const int* __restrict__ x, const int* __restrict__ types, int n)
{
    __shared__ unsigned h[NB];
    for (int i = threadIdx.x; i < NB; i += blockDim.x) h[i] = 0;
    __syncthreads();

    int idx = blockIdx.x * blockDim.x + threadIdx.x;
    int stride = gridDim.x * blockDim.x;
    for (int i = idx; i < n; i += stride) {
        int row = types[i] * VOCAB + x[i];
        atomicAdd(&h[row >> SHIFT], 1u);
    }
    __syncthreads();
    for (int i = threadIdx.x; i < NB; i += blockDim.x)
        if (h[i]) atomicAdd(&g_hist[i], h[i]);
}

// ---------------- pass 2: exclusive scan (single block) ---------------------
__global__ void __launch_bounds__(NB)
scan_kernel()
{
    __shared__ unsigned s[NB];
    int t = threadIdx.x;
    unsigned v = g_hist[t];
    s[t] = v;
    __syncthreads();
    for (int d = 1; d < NB; d <<= 1) {
        unsigned add = (t >= d) ? s[t - d] : 0u;
        __syncthreads();
        s[t] += add;
        __syncthreads();
    }
    g_cursors[t] = s[t] - v;    // exclusive prefix = bucket start
}

// ---------------- pass 3: scatter records into bucket order -----------------
__global__ void __launch_bounds__(256)
scatter_kernel(const int* __restrict__ x, const int* __restrict__ types, int n)
{
    int i = blockIdx.x * blockDim.x + threadIdx.x;
    if (i >= n) return;
    int row = types[i] * VOCAB + x[i];
    unsigned pos = atomicAdd(&g_cursors[row >> SHIFT], 1u);
    g_records[pos] = make_uint2((unsigned)row, (unsigned)i);
}

// ---------------- pass 4: gather in sorted order (8 rows / warp) ------------
__global__ void __launch_bounds__(256)
gather_kernel(const float4* __restrict__ tables, float4* __restrict__ out, int n)
{
    long long warp = (long long)((blockIdx.x * (unsigned)blockDim.x + threadIdx.x) >> 5);
    int lane = threadIdx.x & 31;
    long long base = warp * 8;
    if (base >= n) return;

    if (base + 7 < n) {
        // 8 records = 64B, broadcast uint4 loads (2 records each)
        const uint4* rp = (const uint4*)(g_records + base);
        uint4 ra = __ldg(rp + 0);
        uint4 rb = __ldg(rp + 1);
        uint4 rc = __ldg(rp + 2);
        uint4 rd = __ldg(rp + 3);

        size_t s0 = (size_t)ra.x * F4_PER_ROW + lane;  size_t d0 = (size_t)ra.y * F4_PER_ROW + lane;
        size_t s1 = (size_t)ra.z * F4_PER_ROW + lane;  size_t d1 = (size_t)ra.w * F4_PER_ROW + lane;
        size_t s2 = (size_t)rb.x * F4_PER_ROW + lane;  size_t d2 = (size_t)rb.y * F4_PER_ROW + lane;
        size_t s3 = (size_t)rb.z * F4_PER_ROW + lane;  size_t d3 = (size_t)rb.w * F4_PER_ROW + lane;
        size_t s4 = (size_t)rc.x * F4_PER_ROW + lane;  size_t d4 = (size_t)rc.y * F4_PER_ROW + lane;
        size_t s5 = (size_t)rc.z * F4_PER_ROW + lane;  size_t d5 = (size_t)rc.w * F4_PER_ROW + lane;
        size_t s6 = (size_t)rd.x * F4_PER_ROW + lane;  size_t d6 = (size_t)rd.y * F4_PER_ROW + lane;
        size_t s7 = (size_t)rd.z * F4_PER_ROW + lane;  size_t d7 = (size_t)rd.w * F4_PER_ROW + lane;

        // 8 independent 512B row reads — bucket-ordered, so reuse hits L2
        float4 v0 = __ldg(&tables[s0]);
        float4 v1 = __ldg(&tables[s1]);
        float4 v2 = __ldg(&tables[s2]);
        float4 v3 = __ldg(&tables[s3]);
        float4 v4 = __ldg(&tables[s4]);
        float4 v5 = __ldg(&tables[s5]);
        float4 v6 = __ldg(&tables[s6]);
        float4 v7 = __ldg(&tables[s7]);

        // scattered-by-n but per-row fully coalesced 512B bursts, evict-first
        __stcs(&out[d0], v0);
        __stcs(&out[d1], v1);
        __stcs(&out[d2], v2);
        __stcs(&out[d3], v3);
        __stcs(&out[d4], v4);
        __stcs(&out[d5], v5);
        __stcs(&out[d6], v6);
        __stcs(&out[d7], v7);
    } else {
        for (long long p = base; p < n; p++) {
            uint2 r = g_records[p];
            float4 v = __ldg(&tables[(size_t)r.x * F4_PER_ROW + lane]);
            __stcs(&out[(size_t)r.y * F4_PER_ROW + lane], v);
        }
    }
}

// ---------------- fallback: direct gather (n > MAXN safety) -----------------
__global__ void __launch_bounds__(256)
direct_kernel(const int* __restrict__ x, const int* __restrict__ types,
              const float4* __restrict__ tables, float4* __restrict__ out, int n)
{
    long long warp = (long long)((blockIdx.x * (unsigned)blockDim.x + threadIdx.x) >> 5);
    int lane = threadIdx.x & 31;
    long long base = warp * 4;
    if (base >= n) return;
    for (long long r = base; r < n && r < base + 4; r++) {
        int xi = __ldg(&x[r]);
        int ti = __ldg(&types[r]);
        float4 v = __ldg(&tables[((size_t)ti * VOCAB + (size_t)xi) * F4_PER_ROW + lane]);
        __stcs(&out[(size_t)r * F4_PER_ROW + lane], v);
    }
}

extern "C" void kernel_launch(void* const* d_in, const int* in_sizes, int n_in,
                              void* d_out, int out_size)
{
    const int*    x      = (const int*)d_in[0];
    const int*    types  = (const int*)d_in[1];
    const float4* tables = (const float4*)d_in[2];
    float4*       out    = (float4*)d_out;

    int n = in_sizes[0];

    if (n > MAXN) {
        long long warps = ((long long)n + 3) / 4;
        int grid = (int)((warps * 32 + 255) / 256);
        direct_kernel<<<grid, 256>>>(x, types, tables, out, n);
        return;
    }

    init_kernel<<<(NB + 255) / 256, 256>>>();
    hist_kernel<<<296, 256>>>(x, types, n);
    scan_kernel<<<1, NB>>>();
    scatter_kernel<<<(n + 255) / 256, 256>>>(x, types, n);

    long long warps = ((long long)n + 7) / 8;
    int grid = (int)((warps * 32 + 255) / 256);
    gather_kernel<<<grid, 256>>>(tables, out, n);
}

// round 17
// speedup vs baseline: 1.5924x; 1.5924x over previous
#include <cuda_runtime.h>
#include <cstdint>

// HeteroEmbedding: out[n] = tables[types[n], x[n]]  (row 0 zeroed -> mask implicit).
//
// Inputs: d_in[0] x int32[N], d_in[1] types int32[N], d_in[2] tables f32[8,50000,128]
// Output: f32[N,128]
//
// Counting-sort-by-table-row-bucket, then bucket-ordered gather so each table
// row's ~5x reuse hits L2 (R15: gather 265->~170us). R15's scatter died on
// global atomics (190us @ 1.1% DRAM) -> replaced with deterministic two-level
// offsets: per-block smem histograms + one scan kernel; scatter uses ONLY
// shared-memory atomics. No cross-replay state; no device allocs.

#define VOCAB 50000
#define EMBED 128
#define F4_PER_ROW (EMBED / 4)
#define NB 1024
#define SHIFT 9                 // bucket = table_row >> 9 (782 live buckets)
#define NBLK 296                // partition blocks (2 per SM)
#define MAXN 2000000

__device__ unsigned g_bh[NBLK * NB];   // per-(block,bucket) counts -> start offsets
__device__ uint2    g_records[MAXN];   // {table_row, n}

// ---------------- pass 1: per-block histogram -------------------------------
__global__ void __launch_bounds__(256)
blockhist_kernel(const int* __restrict__ x, const int* __restrict__ types, int n)
{
    __shared__ unsigned h[NB];
    for (int i = threadIdx.x; i < NB; i += 256) h[i] = 0;
    __syncthreads();

    int chunk = (n + NBLK - 1) / NBLK;
    int lo = blockIdx.x * chunk;
    int hi = min(lo + chunk, n);
    for (int i = lo + threadIdx.x; i < hi; i += 256) {
        int row = types[i] * VOCAB + x[i];
        atomicAdd(&h[row >> SHIFT], 1u);
    }
    __syncthreads();
    for (int i = threadIdx.x; i < NB; i += 256)
        g_bh[blockIdx.x * NB + i] = h[i];
}

// ---------------- pass 2: offsets (one block, thread = bucket) --------------
__global__ void __launch_bounds__(NB)
scan_kernel()
{
    __shared__ unsigned s[NB];
    int t = threadIdx.x;

    // total count for this bucket across all partition blocks (coalesced)
    unsigned total = 0;
    for (int b = 0; b < NBLK; b++) total += g_bh[b * NB + t];

    // block-wide exclusive scan of bucket totals
    s[t] = total;
    __syncthreads();
    for (int d = 1; d < NB; d <<= 1) {
        unsigned add = (t >= d) ? s[t - d] : 0u;
        __syncthreads();
        s[t] += add;
        __syncthreads();
    }
    unsigned run = s[t] - total;   // exclusive prefix = bucket start

    // rewrite per-(block,bucket) counts as start offsets
    for (int b = 0; b < NBLK; b++) {
        unsigned c = g_bh[b * NB + t];
        g_bh[b * NB + t] = run;
        run += c;
    }
}

// ---------------- pass 3: scatter (smem atomics only) -----------------------
__global__ void __launch_bounds__(256)
scatter_kernel(const int* __restrict__ x, const int* __restrict__ types, int n)
{
    __shared__ unsigned cur[NB];
    for (int i = threadIdx.x; i < NB; i += 256)
        cur[i] = g_bh[blockIdx.x * NB + i];
    __syncthreads();

    int chunk = (n + NBLK - 1) / NBLK;
    int lo = blockIdx.x * chunk;
    int hi = min(lo + chunk, n);
    for (int i = lo + threadIdx.x; i < hi; i += 256) {
        int row = types[i] * VOCAB + x[i];
        unsigned pos = atomicAdd(&cur[row >> SHIFT], 1u);
        g_records[pos] = make_uint2((unsigned)row, (unsigned)i);
    }
}

// ---------------- pass 4: bucket-ordered gather (8 rows / warp) -------------
__global__ void __launch_bounds__(256)
gather_kernel(const float4* __restrict__ tables, float4* __restrict__ out, int n)
{
    long long warp = (long long)((blockIdx.x * (unsigned)blockDim.x + threadIdx.x) >> 5);
    int lane = threadIdx.x & 31;
    long long base = warp * 8;
    if (base >= n) return;

    if (base + 7 < n) {
        const uint4* rp = (const uint4*)(g_records + base);
        uint4 ra = __ldg(rp + 0);
        uint4 rb = __ldg(rp + 1);
        uint4 rc = __ldg(rp + 2);
        uint4 rd = __ldg(rp + 3);

        size_t s0 = (size_t)ra.x * F4_PER_ROW + lane;  size_t d0 = (size_t)ra.y * F4_PER_ROW + lane;
        size_t s1 = (size_t)ra.z * F4_PER_ROW + lane;  size_t d1 = (size_t)ra.w * F4_PER_ROW + lane;
        size_t s2 = (size_t)rb.x * F4_PER_ROW + lane;  size_t d2 = (size_t)rb.y * F4_PER_ROW + lane;
        size_t s3 = (size_t)rb.z * F4_PER_ROW + lane;  size_t d3 = (size_t)rb.w * F4_PER_ROW + lane;
        size_t s4 = (size_t)rc.x * F4_PER_ROW + lane;  size_t d4 = (size_t)rc.y * F4_PER_ROW + lane;
        size_t s5 = (size_t)rc.z * F4_PER_ROW + lane;  size_t d5 = (size_t)rc.w * F4_PER_ROW + lane;
        size_t s6 = (size_t)rd.x * F4_PER_ROW + lane;  size_t d6 = (size_t)rd.y * F4_PER_ROW + lane;
        size_t s7 = (size_t)rd.z * F4_PER_ROW + lane;  size_t d7 = (size_t)rd.w * F4_PER_ROW + lane;

        // 8 independent 512B row reads — bucket-ordered, reuse hits L2
        float4 v0 = __ldg(&tables[s0]);
        float4 v1 = __ldg(&tables[s1]);
        float4 v2 = __ldg(&tables[s2]);
        float4 v3 = __ldg(&tables[s3]);
        float4 v4 = __ldg(&tables[s4]);
        float4 v5 = __ldg(&tables[s5]);
        float4 v6 = __ldg(&tables[s6]);
        float4 v7 = __ldg(&tables[s7]);

        // per-row fully coalesced 512B bursts, evict-first
        __stcs(&out[d0], v0);
        __stcs(&out[d1], v1);
        __stcs(&out[d2], v2);
        __stcs(&out[d3], v3);
        __stcs(&out[d4], v4);
        __stcs(&out[d5], v5);
        __stcs(&out[d6], v6);
        __stcs(&out[d7], v7);
    } else {
        for (long long p = base; p < n; p++) {
            uint2 r = g_records[p];
            float4 v = __ldg(&tables[(size_t)r.x * F4_PER_ROW + lane]);
            __stcs(&out[(size_t)r.y * F4_PER_ROW + lane], v);
        }
    }
}

// ---------------- fallback: direct gather (n > MAXN safety) -----------------
__global__ void __launch_bounds__(256)
direct_kernel(const int* __restrict__ x, const int* __restrict__ types,
              const float4* __restrict__ tables, float4* __restrict__ out, int n)
{
    long long warp = (long long)((blockIdx.x * (unsigned)blockDim.x + threadIdx.x) >> 5);
    int lane = threadIdx.x & 31;
    long long base = warp * 4;
    if (base >= n) return;
    for (long long r = base; r < n && r < base + 4; r++) {
        int xi = __ldg(&x[r]);
        int ti = __ldg(&types[r]);
        float4 v = __ldg(&tables[((size_t)ti * VOCAB + (size_t)xi) * F4_PER_ROW + lane]);
        __stcs(&out[(size_t)r * F4_PER_ROW + lane], v);
    }
}

extern "C" void kernel_launch(void* const* d_in, const int* in_sizes, int n_in,
                              void* d_out, int out_size)
{
    const int*    x      = (const int*)d_in[0];
    const int*    types  = (const int*)d_in[1];
    const float4* tables = (const float4*)d_in[2];
    float4*       out    = (float4*)d_out;

    int n = in_sizes[0];

    if (n > MAXN) {
        long long warps = ((long long)n + 3) / 4;
        int grid = (int)((warps * 32 + 255) / 256);
        direct_kernel<<<grid, 256>>>(x, types, tables, out, n);
        return;
    }

    blockhist_kernel<<<NBLK, 256>>>(x, types, n);
    scan_kernel<<<1, NB>>>();
    scatter_kernel<<<NBLK, 256>>>(x, types, n);

    long long warps = ((long long)n + 7) / 8;
    int grid = (int)((warps * 32 + 255) / 256);
    gather_kernel<<<grid, 256>>>(tables, out, n);
}